// round 15
// baseline (speedup 1.0000x reference)
#include <cuda_runtime.h>

#define N_Pc  2048
#define N_Wc  89
#define N_ALLc 2137
#define BATCHc 16384
#define E2c   768
#define UWc   313

// output region offsets (floats), in tuple order:
// output1_new[16384,64], output2_new[16384,64], x_temp[16384,5],
// attn_pp[8,2048,2048], attn_wp[8,2137,2137], x[16384,256]
#define O1N_OFF 0L
#define O2N_OFF 1048576L
#define XT_OFF  2097152L
#define APP_OFF 2179072L
#define AWP_OFF 35733504L
#define X_OFF   72267656L

// -------------------- scratch (device globals, no allocation) --------------------
__device__ float g_wt1[256 * 256];
__device__ float g_wt2[256 * 256];
__device__ float g_hp1[N_Pc * 256];
__device__ float g_hp2[N_ALLc * 256];
__device__ float g_h1wp[N_ALLc * 256];
__device__ float g_es1[8 * N_Pc];
__device__ float g_ed1[8 * N_Pc];
__device__ float g_es2[8 * N_ALLc];
__device__ float g_ed2[8 * N_ALLc];
__device__ float g_h2w[N_Wc * 32];
__device__ float g_outcat[BATCHc * 256];
__device__ float g_tg[BATCHc * 128];

// -------------------- fast exp on FMA pipe (no MUFU) --------------------
__device__ __forceinline__ float fast_exp(float x) {
    float y = x * 1.4426950408889634f;           // log2(e)
    float t = y + 12582912.0f;                    // round to nearest int (magic)
    int   ei = __float_as_int(t) - 0x4B400000;    // integer part
    float r = t - 12582912.0f;
    float g = y - r;                              // g in [-0.5, 0.5]
    float p = 1.3333558146e-3f;                   // 2^g Taylor (ln2^k / k!)
    p = fmaf(p, g, 9.6181291076e-3f);
    p = fmaf(p, g, 5.5504108664e-2f);
    p = fmaf(p, g, 2.4022650696e-1f);
    p = fmaf(p, g, 6.9314718056e-1f);
    p = fmaf(p, g, 1.0f);
    return p * __int_as_float(0x3f800000 + (ei << 23));
}

// -------------------- small helper kernels --------------------
__global__ void wtrans_kernel(const float* __restrict__ w, float* __restrict__ wt) {
    int idx = blockIdx.x * 256 + threadIdx.x;     // 65536 total
    int k = idx >> 8;
    int j = idx & 255;
    wt[idx] = w[((j >> 5) * 256 + k) * 32 + (j & 31)];
}

__global__ void copy_kernel(float* __restrict__ dst, const float* __restrict__ src, int n) {
    int i = blockIdx.x * 256 + threadIdx.x;
    if (i < n) dst[i] = src[i];
}

// e_src / e_dst: one block per node n, warp = head
__global__ void esd_kernel(const float* __restrict__ hp,
                           const float* __restrict__ a_src,
                           const float* __restrict__ a_dst,
                           float* __restrict__ e_src,
                           float* __restrict__ e_dst, int N) {
    int n = blockIdx.x;
    int warp = threadIdx.x >> 5, lane = threadIdx.x & 31;
    float v = hp[(long)n * 256 + warp * 32 + lane];
    float s = v * a_src[warp * 32 + lane];
    float d = v * a_dst[warp * 32 + lane];
#pragma unroll
    for (int off = 16; off; off >>= 1) {
        s += __shfl_xor_sync(0xffffffffu, s, off);
        d += __shfl_xor_sync(0xffffffffu, d, off);
    }
    if (lane == 0) {
        e_src[warp * N + n] = s;
        e_dst[warp * N + n] = d;
    }
}

// -------------------- GAT attention kernel --------------------
// MODE 0: GAT1 -> elu(out+bias) into g_h1wp rows [89..]
// MODE 1: GAT2 -> mean over heads into g_h2w, only rows < 89 accumulate
template <int MODE>
__global__ void gat_kernel(const float* __restrict__ hp,
                           const float* __restrict__ e_src,
                           const float* __restrict__ e_dst,
                           const int* __restrict__ adj,
                           float* __restrict__ attn_out,
                           float* __restrict__ feat_out,
                           const float* __restrict__ bias,
                           int N) {
    extern __shared__ float smem[];
    const int MW = (N + 31) >> 5;
    float4* p4 = (float4*)smem;                 // N float4 (p for 4 rows)
    float* fp = smem + 4 * N;
    unsigned* mask = (unsigned*)fp;             // 4*MW words
    float* racc = fp + 4 * MW;                  // 8 warps * 128
    float* wsum = racc + 1024;                  // 8 warps * 4
    float* sinv = wsum + 32;                    // 4
    float* hacc = sinv + 4;                     // 128

    const int tid = threadIdx.x;
    const int warp = tid >> 5;
    const int lane = tid & 31;
    const int row0 = blockIdx.x * 4;

    // build adjacency bitmasks for 4 rows
#pragma unroll
    for (int r = 0; r < 4; r++) {
        int row = row0 + r;
        for (int base = warp * 32; base < MW * 32; base += 256) {
            int m = base + lane;
            int v = (row < N && m < N) ? adj[(long)row * N + m] : 0;
            unsigned bal = __ballot_sync(0xffffffffu, v > 0);
            if (lane == 0) mask[r * MW + (base >> 5)] = bal;
        }
    }
    if (MODE == 1 && tid < 128) hacc[tid] = 0.f;
    __syncthreads();

    for (int h = 0; h < 8; h++) {
        float es0 = (row0 + 0 < N) ? e_src[h * N + row0 + 0] : 0.f;
        float es1 = (row0 + 1 < N) ? e_src[h * N + row0 + 1] : 0.f;
        float es2 = (row0 + 2 < N) ? e_src[h * N + row0 + 2] : 0.f;
        float es3 = (row0 + 3 < N) ? e_src[h * N + row0 + 3] : 0.f;
        float ls0 = 0.f, ls1 = 0.f, ls2 = 0.f, ls3 = 0.f;

        for (int m = tid; m < N; m += 256) {
            float ed = e_dst[h * N + m];
            int w = m >> 5;
            unsigned bit = 1u << (m & 31);
            unsigned m0b = mask[0 * MW + w];
            unsigned m1b = mask[1 * MW + w];
            unsigned m2b = mask[2 * MW + w];
            unsigned m3b = mask[3 * MW + w];
            float4 pv;
            float e;
            e = es0 + ed; e = fmaxf(e, 0.2f * e);
            pv.x = (m0b & bit) ? fast_exp(e) : 0.f;
            e = es1 + ed; e = fmaxf(e, 0.2f * e);
            pv.y = (m1b & bit) ? fast_exp(e) : 0.f;
            e = es2 + ed; e = fmaxf(e, 0.2f * e);
            pv.z = (m2b & bit) ? fast_exp(e) : 0.f;
            e = es3 + ed; e = fmaxf(e, 0.2f * e);
            pv.w = (m3b & bit) ? fast_exp(e) : 0.f;
            ls0 += pv.x; ls1 += pv.y; ls2 += pv.z; ls3 += pv.w;
            p4[m] = pv;
        }
#pragma unroll
        for (int off = 16; off; off >>= 1) {
            ls0 += __shfl_xor_sync(0xffffffffu, ls0, off);
            ls1 += __shfl_xor_sync(0xffffffffu, ls1, off);
            ls2 += __shfl_xor_sync(0xffffffffu, ls2, off);
            ls3 += __shfl_xor_sync(0xffffffffu, ls3, off);
        }
        if (lane == 0) {
            wsum[warp * 4 + 0] = ls0;
            wsum[warp * 4 + 1] = ls1;
            wsum[warp * 4 + 2] = ls2;
            wsum[warp * 4 + 3] = ls3;
        }
        __syncthreads();
        if (tid < 4) {
            float s = 0.f;
#pragma unroll
            for (int w = 0; w < 8; w++) s += wsum[w * 4 + tid];
            sinv[tid] = (s > 0.f) ? (1.f / s) : 0.f;
        }
        __syncthreads();

        float i0 = sinv[0], i1 = sinv[1], i2 = sinv[2], i3 = sinv[3];
        long ab = ((long)h * N + row0) * (long)N;
        int nvalid = N - row0;
        for (int m = tid; m < N; m += 256) {
            float4 pv = p4[m];
            attn_out[ab + m] = pv.x * i0;
            if (nvalid > 1) attn_out[ab + (long)N + m] = pv.y * i1;
            if (nvalid > 2) attn_out[ab + 2L * N + m] = pv.z * i2;
            if (nvalid > 3) attn_out[ab + 3L * N + m] = pv.w * i3;
        }

        bool do_acc = (MODE == 0) || (row0 < N_Wc);
        if (do_acc) {
            float a0 = 0.f, a1 = 0.f, a2 = 0.f, a3 = 0.f;
            const float* hpc = hp + h * 32 + lane;
            for (int m = warp; m < N; m += 8) {
                float hv = hpc[(long)m * 256];
                float4 pv = p4[m];
                a0 = fmaf(pv.x, hv, a0);
                a1 = fmaf(pv.y, hv, a1);
                a2 = fmaf(pv.z, hv, a2);
                a3 = fmaf(pv.w, hv, a3);
            }
            __syncthreads();  // protect racc vs previous head's readers
            racc[warp * 128 + lane]      = a0;
            racc[warp * 128 + 32 + lane] = a1;
            racc[warp * 128 + 64 + lane] = a2;
            racc[warp * 128 + 96 + lane] = a3;
            __syncthreads();
            if (tid < 128) {
                int r = tid >> 5, o = tid & 31;
                float s = 0.f;
#pragma unroll
                for (int w = 0; w < 8; w++) s += racc[w * 128 + tid];
                s *= sinv[r];
                int row = row0 + r;
                if (MODE == 0) {
                    if (row < N) {
                        float v = s + bias[o];
                        feat_out[(long)(N_Wc + row) * 256 + h * 32 + o] =
                            (v > 0.f) ? v : (fast_exp(v) - 1.f);
                    }
                } else {
                    hacc[tid] += s;
                }
            }
        }
        __syncthreads();  // p4 / sinv reuse next head
    }

    if (MODE == 1 && tid < 128) {
        int r = tid >> 5, o = tid & 31;
        int row = row0 + r;
        if (row < N_Wc) feat_out[row * 32 + o] = hacc[tid] * 0.125f + bias[o];
    }
}

// -------------------- generic tiled SGEMM --------------------
// C[M,N] = A[M,K] @ B[K,N] (+bias) (+relu), A lda, B row-major ldb, C ldc
template <int BM, int BN, int BK, int TM, int TN, int ACT>
__global__ void sgemm_kernel(const float* __restrict__ A, int lda,
                             const float* __restrict__ B, int ldb,
                             float* __restrict__ C, int ldc,
                             int M, int N, int K,
                             const float* __restrict__ bias) {
    __shared__ __align__(16) float As[BK][BM];
    __shared__ __align__(16) float Bs[BK][BN];
    constexpr int THREADS = (BM / TM) * (BN / TN);
    const int tid = threadIdx.x;
    const int m0 = blockIdx.x * BM;
    const int n0 = blockIdx.y * BN;
    const int tx = tid % (BN / TN);
    const int ty = tid / (BN / TN);

    float acc[TM][TN];
#pragma unroll
    for (int i = 0; i < TM; i++)
#pragma unroll
        for (int j = 0; j < TN; j++) acc[i][j] = 0.f;

    constexpr int LA = BM * BK / (4 * THREADS);
    constexpr int LB = BN * BK / (4 * THREADS);

    for (int k0 = 0; k0 < K; k0 += BK) {
#pragma unroll
        for (int i = 0; i < LA; i++) {
            int idx = tid + i * THREADS;
            int arow = idx / (BK / 4);
            int acol4 = idx % (BK / 4);
            float4 v = make_float4(0.f, 0.f, 0.f, 0.f);
            int grow = m0 + arow;
            if (grow < M)
                v = *(const float4*)(A + (long)grow * lda + k0 + acol4 * 4);
            As[acol4 * 4 + 0][arow] = v.x;
            As[acol4 * 4 + 1][arow] = v.y;
            As[acol4 * 4 + 2][arow] = v.z;
            As[acol4 * 4 + 3][arow] = v.w;
        }
#pragma unroll
        for (int i = 0; i < LB; i++) {
            int idx = tid + i * THREADS;
            int brow = idx / (BN / 4);
            int bcol4 = idx % (BN / 4);
            *(float4*)&Bs[brow][bcol4 * 4] =
                *(const float4*)(B + (long)(k0 + brow) * ldb + n0 + bcol4 * 4);
        }
        __syncthreads();
#pragma unroll
        for (int k = 0; k < BK; k++) {
            float ra[TM], rb[TN];
#pragma unroll
            for (int i = 0; i < TM; i++) ra[i] = As[k][ty * TM + i];
#pragma unroll
            for (int j = 0; j < TN; j++) rb[j] = Bs[k][tx * TN + j];
#pragma unroll
            for (int i = 0; i < TM; i++)
#pragma unroll
                for (int j = 0; j < TN; j++) acc[i][j] = fmaf(ra[i], rb[j], acc[i][j]);
        }
        __syncthreads();
    }
#pragma unroll
    for (int i = 0; i < TM; i++) {
        int row = m0 + ty * TM + i;
        if (row >= M) continue;
#pragma unroll
        for (int j = 0; j < TN; j++) {
            int col = n0 + tx * TN + j;
            float v = acc[i][j];
            if (bias) v += bias[col];
            if (ACT == 1) v = fmaxf(v, 0.f);
            C[(long)row * ldc + col] = v;
        }
    }
}

// -------------------- x normalization --------------------
// x0 = uwa[:, :89] @ h2w ; x = [x0, uwa[:,89:]] / rowsum
__global__ void xnorm_kernel(const float* __restrict__ uwa,
                             const float* __restrict__ h2w,
                             float* __restrict__ xout) {
    __shared__ float sh2[N_Wc * 32];
    __shared__ float srow[8][320];
    int tid = threadIdx.x;
    for (int i = tid; i < N_Wc * 32; i += 256) sh2[i] = h2w[i];
    int warp = tid >> 5, lane = tid & 31;
    int b = blockIdx.x * 8 + warp;
    for (int k = lane; k < UWc; k += 32) srow[warp][k] = uwa[(long)b * UWc + k];
    __syncthreads();

    float x0 = 0.f;
    for (int k = 0; k < N_Wc; k++) x0 = fmaf(srow[warp][k], sh2[k * 32 + lane], x0);
    float part = x0;
    for (int k = N_Wc + lane; k < UWc; k += 32) part += srow[warp][k];
#pragma unroll
    for (int off = 16; off; off >>= 1) part += __shfl_xor_sync(0xffffffffu, part, off);
    float inv = 1.f / part;
    xout[(long)b * 256 + lane] = x0 * inv;
    for (int k = lane; k < 224; k += 32)
        xout[(long)b * 256 + 32 + k] = srow[warp][N_Wc + k] * inv;
}

// -------------------- x_temp final: t[16384,128] @ W_fb[128,5] + b --------------------
__global__ void xt_kernel(const float* __restrict__ t,
                          const float* __restrict__ Wfb,
                          const float* __restrict__ bfb,
                          float* __restrict__ out) {
    __shared__ float sw[128 * 5];
    __shared__ float sb[5];
    int tid = threadIdx.x;
    for (int i = tid; i < 640; i += 256) sw[i] = Wfb[i];
    if (tid < 5) sb[tid] = bfb[tid];
    __syncthreads();
    int warp = tid >> 5, lane = tid & 31;
    int b = blockIdx.x * 8 + warp;
    float acc[5] = {0.f, 0.f, 0.f, 0.f, 0.f};
    for (int k = lane; k < 128; k += 32) {
        float tv = t[(long)b * 128 + k];
#pragma unroll
        for (int j = 0; j < 5; j++) acc[j] = fmaf(tv, sw[k * 5 + j], acc[j]);
    }
#pragma unroll
    for (int off = 16; off; off >>= 1)
#pragma unroll
        for (int j = 0; j < 5; j++) acc[j] += __shfl_xor_sync(0xffffffffu, acc[j], off);
    if (lane < 5) out[(long)b * 5 + lane] = acc[lane] + sb[lane];
}

// -------------------- host launch --------------------
static inline int cdiv(int a, int b) { return (a + b - 1) / b; }

extern "C" void kernel_launch(void* const* d_in, const int* in_sizes, int n_in,
                              void* d_out, int out_size) {
    const float* pern  = (const float*)d_in[0];
    const float* wordf = (const float*)d_in[1];
    const int*   padj  = (const int*)d_in[2];
    const int*   wpadj = (const int*)d_in[3];
    const float* uwa   = (const float*)d_in[4];
    const float* sent  = (const float*)d_in[5];
    const float* w1    = (const float*)d_in[6];
    const float* as1   = (const float*)d_in[7];
    const float* ad1   = (const float*)d_in[8];
    const float* b1    = (const float*)d_in[9];
    const float* w2    = (const float*)d_in[10];
    const float* as2   = (const float*)d_in[11];
    const float* ad2   = (const float*)d_in[12];
    const float* b2    = (const float*)d_in[13];
    const float* Ws1   = (const float*)d_in[14];
    const float* bs1   = (const float*)d_in[15];
    const float* Ws2   = (const float*)d_in[16];
    const float* bs2   = (const float*)d_in[17];
    const float* Wf1   = (const float*)d_in[18];
    const float* bf1   = (const float*)d_in[19];
    const float* Wfa   = (const float*)d_in[20];
    const float* bfa   = (const float*)d_in[21];
    const float* Wfb   = (const float*)d_in[22];
    const float* bfb   = (const float*)d_in[23];
    float* out = (float*)d_out;

    float *wt1, *wt2, *hp1, *hp2, *h1wp, *es1, *ed1, *es2, *ed2, *h2w, *outcat, *tg;
    cudaGetSymbolAddress((void**)&wt1, g_wt1);
    cudaGetSymbolAddress((void**)&wt2, g_wt2);
    cudaGetSymbolAddress((void**)&hp1, g_hp1);
    cudaGetSymbolAddress((void**)&hp2, g_hp2);
    cudaGetSymbolAddress((void**)&h1wp, g_h1wp);
    cudaGetSymbolAddress((void**)&es1, g_es1);
    cudaGetSymbolAddress((void**)&ed1, g_ed1);
    cudaGetSymbolAddress((void**)&es2, g_es2);
    cudaGetSymbolAddress((void**)&ed2, g_ed2);
    cudaGetSymbolAddress((void**)&h2w, g_h2w);
    cudaGetSymbolAddress((void**)&outcat, g_outcat);
    cudaGetSymbolAddress((void**)&tg, g_tg);

    // weight transposes + word feature copy
    wtrans_kernel<<<256, 256>>>(w1, wt1);
    wtrans_kernel<<<256, 256>>>(w2, wt2);
    copy_kernel<<<cdiv(N_Wc * 256, 256), 256>>>(h1wp, wordf, N_Wc * 256);

    // GAT1: hp1 = pern @ wt1 ; e_src/e_dst ; attention
    sgemm_kernel<128, 128, 16, 8, 8, 0><<<dim3(16, 2), 256>>>(
        pern, 256, wt1, 256, hp1, 256, N_Pc, 256, 256, nullptr);
    esd_kernel<<<N_Pc, 256>>>(hp1, as1, ad1, es1, ed1, N_Pc);
    {
        int MW = (N_Pc + 31) / 32;
        size_t sm = (size_t)(4 * N_Pc + 4 * MW + 1024 + 32 + 4 + 128) * 4;
        gat_kernel<0><<<cdiv(N_Pc, 4), 256, sm>>>(
            hp1, es1, ed1, padj, out + APP_OFF, h1wp, b1, N_Pc);
    }

    // GAT2: hp2 = h1wp @ wt2 ; e ; attention (+ mean rows<89)
    sgemm_kernel<128, 128, 16, 8, 8, 0><<<dim3(17, 2), 256>>>(
        h1wp, 256, wt2, 256, hp2, 256, N_ALLc, 256, 256, nullptr);
    esd_kernel<<<N_ALLc, 256>>>(hp2, as2, ad2, es2, ed2, N_ALLc);
    {
        int MW = (N_ALLc + 31) / 32;
        size_t sm = (size_t)(4 * N_ALLc + 4 * MW + 1024 + 32 + 4 + 128) * 4;
        gat_kernel<1><<<cdiv(N_ALLc, 4), 256, sm>>>(
            hp2, es2, ed2, wpadj, out + AWP_OFF, h2w, b2, N_ALLc);
    }

    // x (normalized) into d_out
    xnorm_kernel<<<BATCHc / 8, 256>>>(uwa, h2w, out + X_OFF);

    // out1 = x @ W_s1 + b_s1 -> outcat[:, :128]
    sgemm_kernel<128, 128, 16, 8, 8, 0><<<dim3(128, 1), 256>>>(
        out + X_OFF, 256, Ws1, 128, outcat, 256, BATCHc, 128, 256, bs1);
    // out2 = sentence @ W_s2 + b_s2 -> outcat[:, 128:]
    sgemm_kernel<128, 128, 16, 8, 8, 0><<<dim3(128, 1), 256>>>(
        sent, 768, Ws2, 128, outcat + 128, 256, BATCHc, 128, 768, bs2);

    // output1_new = out1 @ W_f1 + b_f1 ; output2_new = out2 @ W_f1 + b_f1
    sgemm_kernel<128, 64, 16, 8, 4, 0><<<dim3(128, 1), 256>>>(
        outcat, 256, Wf1, 64, out + O1N_OFF, 64, BATCHc, 64, 128, bf1);
    sgemm_kernel<128, 64, 16, 8, 4, 0><<<dim3(128, 1), 256>>>(
        outcat + 128, 256, Wf1, 64, out + O2N_OFF, 64, BATCHc, 64, 128, bf1);

    // t = relu(outcat @ W_fa + b_fa)
    sgemm_kernel<128, 128, 16, 8, 8, 1><<<dim3(128, 1), 256>>>(
        outcat, 256, Wfa, 128, tg, 128, BATCHc, 128, 256, bfa);

    // x_temp = t @ W_fb + b_fb
    xt_kernel<<<BATCHc / 8, 256>>>(tg, Wfb, bfb, out + XT_OFF);
}

// round 16
// speedup vs baseline: 1.1169x; 1.1169x over previous
#include <cuda_runtime.h>

#define N_Pc  2048
#define N_Wc  89
#define N_ALLc 2137
#define BATCHc 16384
#define E2c   768
#define UWc   313

#define O1N_OFF 0L
#define O2N_OFF 1048576L
#define XT_OFF  2097152L
#define APP_OFF 2179072L
#define AWP_OFF 35733504L
#define X_OFF   72267656L

// -------------------- scratch --------------------
__device__ float g_wt1[256 * 256];
__device__ float g_wt2[256 * 256];
__device__ float g_hp1[N_Pc * 256];
__device__ float g_hp2[N_ALLc * 256];
__device__ float g_h1wp[N_ALLc * 256];
__device__ float g_es1[8 * N_Pc];
__device__ float g_ed1[8 * N_Pc];
__device__ float g_es2[8 * N_ALLc];
__device__ float g_ed2[8 * N_ALLc];
__device__ float g_h2w[N_Wc * 32];
__device__ float g_outcat[BATCHc * 256];
__device__ float g_tg[BATCHc * 128];

// -------------------- fast exp (FMA pipe, no MUFU) --------------------
__device__ __forceinline__ float fast_exp(float x) {
    float y = x * 1.4426950408889634f;
    float t = y + 12582912.0f;
    int   ei = __float_as_int(t) - 0x4B400000;
    float r = t - 12582912.0f;
    float g = y - r;
    float p = 1.3333558146e-3f;
    p = fmaf(p, g, 9.6181291076e-3f);
    p = fmaf(p, g, 5.5504108664e-2f);
    p = fmaf(p, g, 2.4022650696e-1f);
    p = fmaf(p, g, 6.9314718056e-1f);
    p = fmaf(p, g, 1.0f);
    return p * __int_as_float(0x3f800000 + (ei << 23));
}

// -------------------- helpers --------------------
__global__ void wtrans_kernel(const float* __restrict__ w, float* __restrict__ wt) {
    int idx = blockIdx.x * 256 + threadIdx.x;
    int k = idx >> 8;
    int j = idx & 255;
    wt[idx] = w[((j >> 5) * 256 + k) * 32 + (j & 31)];
}

__global__ void copy_kernel(float* __restrict__ dst, const float* __restrict__ src, int n) {
    int i = blockIdx.x * 256 + threadIdx.x;
    if (i < n) dst[i] = src[i];
}

__global__ void esd_kernel(const float* __restrict__ hp,
                           const float* __restrict__ a_src,
                           const float* __restrict__ a_dst,
                           float* __restrict__ e_src,
                           float* __restrict__ e_dst, int N) {
    int n = blockIdx.x;
    int warp = threadIdx.x >> 5, lane = threadIdx.x & 31;
    float v = hp[(long)n * 256 + warp * 32 + lane];
    float s = v * a_src[warp * 32 + lane];
    float d = v * a_dst[warp * 32 + lane];
#pragma unroll
    for (int off = 16; off; off >>= 1) {
        s += __shfl_xor_sync(0xffffffffu, s, off);
        d += __shfl_xor_sync(0xffffffffu, d, off);
    }
    if (lane == 0) {
        e_src[warp * N + n] = s;
        e_dst[warp * N + n] = d;
    }
}

// -------------------- GAT kernel: 8 rows/block --------------------
// smem: p4A[N] (rows0-3), p4B[N] (rows4-7), mask[8*MW], wsum[64], sinv[8],
//       racc[2048], hacc[256]
template <int MODE>
__global__ void gat_kernel(const float* __restrict__ hp,
                           const float* __restrict__ e_src,
                           const float* __restrict__ e_dst,
                           const int* __restrict__ adj,
                           float* __restrict__ attn_out,
                           float* __restrict__ feat_out,
                           const float* __restrict__ bias,
                           int N) {
    extern __shared__ float smem[];
    const int MW = (N + 31) >> 5;
    float4* p4 = (float4*)smem;                 // 2*N float4
    float* fp = smem + 8 * N;
    unsigned* mask = (unsigned*)fp;             // 8*MW
    float* wsum = fp + 8 * MW;                  // 64
    float* sinv = wsum + 64;                    // 8
    float* racc = sinv + 8;                     // 8 warps * 256
    float* hacc = racc + 2048;                  // 256

    const int tid = threadIdx.x;
    const int warp = tid >> 5;
    const int lane = tid & 31;
    const int row0 = blockIdx.x * 8;
    const int nr = min(8, N - row0);

#pragma unroll
    for (int r = 0; r < 8; r++) {
        int row = row0 + r;
        for (int base = warp * 32; base < MW * 32; base += 256) {
            int m = base + lane;
            int v = (row < N && m < N) ? adj[(long)row * N + m] : 0;
            unsigned bal = __ballot_sync(0xffffffffu, v > 0);
            if (lane == 0) mask[r * MW + (base >> 5)] = bal;
        }
    }
    if (MODE == 1 && tid < 256) hacc[tid] = 0.f;
    __syncthreads();

    const bool do_acc = (MODE == 0) || (row0 < N_Wc);

    for (int h = 0; h < 8; h++) {
        float es[8], ls[8];
#pragma unroll
        for (int r = 0; r < 8; r++) {
            es[r] = (row0 + r < N) ? e_src[h * N + row0 + r] : 0.f;
            ls[r] = 0.f;
        }

        // ---- exp + masking, p into shared ----
        for (int m = tid; m < N; m += 256) {
            float ed = e_dst[h * N + m];
            int w = m >> 5;
            unsigned bit = 1u << (m & 31);
            float pv[8];
#pragma unroll
            for (int r = 0; r < 8; r++) {
                float e = es[r] + ed;
                e = fmaxf(e, 0.2f * e);
                pv[r] = (mask[r * MW + w] & bit) ? fast_exp(e) : 0.f;
                ls[r] += pv[r];
            }
            p4[m]     = make_float4(pv[0], pv[1], pv[2], pv[3]);
            p4[N + m] = make_float4(pv[4], pv[5], pv[6], pv[7]);
        }
#pragma unroll
        for (int off = 16; off; off >>= 1)
#pragma unroll
            for (int r = 0; r < 8; r++) ls[r] += __shfl_xor_sync(0xffffffffu, ls[r], off);
        if (lane == 0)
#pragma unroll
            for (int r = 0; r < 8; r++) wsum[warp * 8 + r] = ls[r];
        __syncthreads();
        if (tid < 8) {
            float s = 0.f;
#pragma unroll
            for (int w = 0; w < 8; w++) s += wsum[w * 8 + tid];
            sinv[tid] = (s > 0.f) ? (1.f / s) : 0.f;
        }
        __syncthreads();

        float sv[8];
#pragma unroll
        for (int r = 0; r < 8; r++) sv[r] = sinv[r];

        // ---- write normalized attention ----
        long ab = ((long)h * N + row0) * (long)N;
        for (int m = tid; m < N; m += 256) {
            float4 pa = p4[m], pb = p4[N + m];
            float pv[8] = {pa.x, pa.y, pa.z, pa.w, pb.x, pb.y, pb.z, pb.w};
#pragma unroll
            for (int r = 0; r < 8; r++)
                if (r < nr) attn_out[ab + (long)r * N + m] = pv[r] * sv[r];
        }

        // ---- out = attn @ hp (unnormalized p, scale at end) ----
        if (do_acc) {
            float a[8];
#pragma unroll
            for (int r = 0; r < 8; r++) a[r] = 0.f;
            const float* hpc = hp + h * 32 + lane;
#pragma unroll 4
            for (int m = warp; m < N; m += 8) {
                float hv = __ldg(hpc + (long)m * 256);
                float4 pa = p4[m], pb = p4[N + m];
                a[0] = fmaf(pa.x, hv, a[0]);
                a[1] = fmaf(pa.y, hv, a[1]);
                a[2] = fmaf(pa.z, hv, a[2]);
                a[3] = fmaf(pa.w, hv, a[3]);
                a[4] = fmaf(pb.x, hv, a[4]);
                a[5] = fmaf(pb.y, hv, a[5]);
                a[6] = fmaf(pb.z, hv, a[6]);
                a[7] = fmaf(pb.w, hv, a[7]);
            }
#pragma unroll
            for (int r = 0; r < 8; r++) racc[warp * 256 + r * 32 + lane] = a[r];
            __syncthreads();
            {
                int r = tid >> 5, o = tid & 31;
                float s = 0.f;
#pragma unroll
                for (int w = 0; w < 8; w++) s += racc[w * 256 + tid];
                s *= sinv[r];
                int row = row0 + r;
                if (MODE == 0) {
                    if (row < N) {
                        float v = s + bias[o];
                        feat_out[(long)(N_Wc + row) * 256 + h * 32 + o] =
                            (v > 0.f) ? v : (fast_exp(v) - 1.f);
                    }
                } else {
                    hacc[tid] += s;
                }
            }
        }
        __syncthreads();
    }

    if (MODE == 1 && tid < 256) {
        int r = tid >> 5, o = tid & 31;
        int row = row0 + r;
        if (row < N_Wc) feat_out[row * 32 + o] = hacc[tid] * 0.125f + bias[o];
    }
}

// -------------------- double-buffered SGEMM --------------------
template <int BM, int BN, int BK, int TM, int TN, int ACT>
__global__ void sgemm2_kernel(const float* __restrict__ A, int lda,
                              const float* __restrict__ B, int ldb,
                              float* __restrict__ C, int ldc,
                              int M, int N, int K,
                              const float* __restrict__ bias) {
    constexpr int THREADS = (BM / TM) * (BN / TN);
    constexpr int LA = BM * BK / (4 * THREADS);
    constexpr int LB = BN * BK / (4 * THREADS);
    __shared__ __align__(16) float As[2][BK][BM];
    __shared__ __align__(16) float Bs[2][BK][BN];
    const int tid = threadIdx.x;
    const int m0 = blockIdx.x * BM;
    const int n0 = blockIdx.y * BN;
    const int tx = tid % (BN / TN);
    const int ty = tid / (BN / TN);

    float4 pa[LA], pb[LB];
    float acc[TM][TN];
#pragma unroll
    for (int i = 0; i < TM; i++)
#pragma unroll
        for (int j = 0; j < TN; j++) acc[i][j] = 0.f;

    // global load into regs for tile at k0
    auto loadG = [&](int k0) {
#pragma unroll
        for (int i = 0; i < LA; i++) {
            int idx = tid + i * THREADS;
            int arow = idx / (BK / 4);
            int acol = (idx % (BK / 4)) * 4;
            int grow = m0 + arow;
            pa[i] = (grow < M) ? *(const float4*)(A + (long)grow * lda + k0 + acol)
                               : make_float4(0.f, 0.f, 0.f, 0.f);
        }
#pragma unroll
        for (int i = 0; i < LB; i++) {
            int idx = tid + i * THREADS;
            int brow = idx / (BN / 4);
            int bcol = (idx % (BN / 4)) * 4;
            pb[i] = *(const float4*)(B + (long)(k0 + brow) * ldb + n0 + bcol);
        }
    };
    auto storeS = [&](int buf) {
#pragma unroll
        for (int i = 0; i < LA; i++) {
            int idx = tid + i * THREADS;
            int arow = idx / (BK / 4);
            int acol = (idx % (BK / 4)) * 4;
            As[buf][acol + 0][arow] = pa[i].x;
            As[buf][acol + 1][arow] = pa[i].y;
            As[buf][acol + 2][arow] = pa[i].z;
            As[buf][acol + 3][arow] = pa[i].w;
        }
#pragma unroll
        for (int i = 0; i < LB; i++) {
            int idx = tid + i * THREADS;
            int brow = idx / (BN / 4);
            int bcol = (idx % (BN / 4)) * 4;
            *(float4*)&Bs[buf][brow][bcol] = pb[i];
        }
    };

    loadG(0);
    storeS(0);
    __syncthreads();

    const int nt = K / BK;
    for (int t = 0; t < nt; t++) {
        int cur = t & 1;
        if (t + 1 < nt) loadG((t + 1) * BK);
#pragma unroll
        for (int k = 0; k < BK; k++) {
            float ra[TM], rb[TN];
#pragma unroll
            for (int i = 0; i < TM; i += 4)
                *(float4*)&ra[i] = *(const float4*)&As[cur][k][ty * TM + i];
#pragma unroll
            for (int j = 0; j < TN; j += 4)
                *(float4*)&rb[j] = *(const float4*)&Bs[cur][k][tx * TN + j];
#pragma unroll
            for (int i = 0; i < TM; i++)
#pragma unroll
                for (int j = 0; j < TN; j++) acc[i][j] = fmaf(ra[i], rb[j], acc[i][j]);
        }
        if (t + 1 < nt) storeS(1 - cur);
        __syncthreads();
    }

#pragma unroll
    for (int i = 0; i < TM; i++) {
        int row = m0 + ty * TM + i;
        if (row >= M) continue;
#pragma unroll
        for (int j = 0; j < TN; j++) {
            int col = n0 + tx * TN + j;
            float v = acc[i][j];
            if (bias) v += bias[col];
            if (ACT == 1) v = fmaxf(v, 0.f);
            C[(long)row * ldc + col] = v;
        }
    }
}

// -------------------- x normalization --------------------
__global__ void xnorm_kernel(const float* __restrict__ uwa,
                             const float* __restrict__ h2w,
                             float* __restrict__ xout) {
    __shared__ float sh2[N_Wc * 32];
    __shared__ float srow[8][320];
    int tid = threadIdx.x;
    for (int i = tid; i < N_Wc * 32; i += 256) sh2[i] = h2w[i];
    int warp = tid >> 5, lane = tid & 31;
    int b = blockIdx.x * 8 + warp;
    for (int k = lane; k < UWc; k += 32) srow[warp][k] = uwa[(long)b * UWc + k];
    __syncthreads();

    float x0 = 0.f;
    for (int k = 0; k < N_Wc; k++) x0 = fmaf(srow[warp][k], sh2[k * 32 + lane], x0);
    float part = x0;
    for (int k = N_Wc + lane; k < UWc; k += 32) part += srow[warp][k];
#pragma unroll
    for (int off = 16; off; off >>= 1) part += __shfl_xor_sync(0xffffffffu, part, off);
    float inv = 1.f / part;
    xout[(long)b * 256 + lane] = x0 * inv;
    for (int k = lane; k < 224; k += 32)
        xout[(long)b * 256 + 32 + k] = srow[warp][N_Wc + k] * inv;
}

// -------------------- x_temp final --------------------
__global__ void xt_kernel(const float* __restrict__ t,
                          const float* __restrict__ Wfb,
                          const float* __restrict__ bfb,
                          float* __restrict__ out) {
    __shared__ float sw[128 * 5];
    __shared__ float sb[5];
    int tid = threadIdx.x;
    for (int i = tid; i < 640; i += 256) sw[i] = Wfb[i];
    if (tid < 5) sb[tid] = bfb[tid];
    __syncthreads();
    int warp = tid >> 5, lane = tid & 31;
    int b = blockIdx.x * 8 + warp;
    float acc[5] = {0.f, 0.f, 0.f, 0.f, 0.f};
    for (int k = lane; k < 128; k += 32) {
        float tv = t[(long)b * 128 + k];
#pragma unroll
        for (int j = 0; j < 5; j++) acc[j] = fmaf(tv, sw[k * 5 + j], acc[j]);
    }
#pragma unroll
    for (int off = 16; off; off >>= 1)
#pragma unroll
        for (int j = 0; j < 5; j++) acc[j] += __shfl_xor_sync(0xffffffffu, acc[j], off);
    if (lane < 5) out[(long)b * 5 + lane] = acc[lane] + sb[lane];
}

// -------------------- host launch --------------------
static inline int cdiv(int a, int b) { return (a + b - 1) / b; }

extern "C" void kernel_launch(void* const* d_in, const int* in_sizes, int n_in,
                              void* d_out, int out_size) {
    const float* pern  = (const float*)d_in[0];
    const float* wordf = (const float*)d_in[1];
    const int*   padj  = (const int*)d_in[2];
    const int*   wpadj = (const int*)d_in[3];
    const float* uwa   = (const float*)d_in[4];
    const float* sent  = (const float*)d_in[5];
    const float* w1    = (const float*)d_in[6];
    const float* as1   = (const float*)d_in[7];
    const float* ad1   = (const float*)d_in[8];
    const float* b1    = (const float*)d_in[9];
    const float* w2    = (const float*)d_in[10];
    const float* as2   = (const float*)d_in[11];
    const float* ad2   = (const float*)d_in[12];
    const float* b2    = (const float*)d_in[13];
    const float* Ws1   = (const float*)d_in[14];
    const float* bs1   = (const float*)d_in[15];
    const float* Ws2   = (const float*)d_in[16];
    const float* bs2   = (const float*)d_in[17];
    const float* Wf1   = (const float*)d_in[18];
    const float* bf1   = (const float*)d_in[19];
    const float* Wfa   = (const float*)d_in[20];
    const float* bfa   = (const float*)d_in[21];
    const float* Wfb   = (const float*)d_in[22];
    const float* bfb   = (const float*)d_in[23];
    float* out = (float*)d_out;

    float *wt1, *wt2, *hp1, *hp2, *h1wp, *es1, *ed1, *es2, *ed2, *h2w, *outcat, *tg;
    cudaGetSymbolAddress((void**)&wt1, g_wt1);
    cudaGetSymbolAddress((void**)&wt2, g_wt2);
    cudaGetSymbolAddress((void**)&hp1, g_hp1);
    cudaGetSymbolAddress((void**)&hp2, g_hp2);
    cudaGetSymbolAddress((void**)&h1wp, g_h1wp);
    cudaGetSymbolAddress((void**)&es1, g_es1);
    cudaGetSymbolAddress((void**)&ed1, g_ed1);
    cudaGetSymbolAddress((void**)&es2, g_es2);
    cudaGetSymbolAddress((void**)&ed2, g_ed2);
    cudaGetSymbolAddress((void**)&h2w, g_h2w);
    cudaGetSymbolAddress((void**)&outcat, g_outcat);
    cudaGetSymbolAddress((void**)&tg, g_tg);

    // raise dynamic smem limit for GAT kernels (idempotent)
    cudaFuncSetAttribute(gat_kernel<0>, cudaFuncAttributeMaxDynamicSharedMemorySize, 96 * 1024);
    cudaFuncSetAttribute(gat_kernel<1>, cudaFuncAttributeMaxDynamicSharedMemorySize, 96 * 1024);

    wtrans_kernel<<<256, 256>>>(w1, wt1);
    wtrans_kernel<<<256, 256>>>(w2, wt2);
    copy_kernel<<<cdiv(N_Wc * 256, 256), 256>>>(h1wp, wordf, N_Wc * 256);

    // GAT1
    sgemm2_kernel<64, 64, 16, 4, 4, 0><<<dim3(32, 4), 256>>>(
        pern, 256, wt1, 256, hp1, 256, N_Pc, 256, 256, nullptr);
    esd_kernel<<<N_Pc, 256>>>(hp1, as1, ad1, es1, ed1, N_Pc);
    {
        int MW = (N_Pc + 31) / 32;
        size_t sm = (size_t)(8 * N_Pc + 8 * MW + 64 + 8 + 2048 + 256) * 4;
        gat_kernel<0><<<cdiv(N_Pc, 8), 256, sm>>>(
            hp1, es1, ed1, padj, out + APP_OFF, h1wp, b1, N_Pc);
    }

    // GAT2
    sgemm2_kernel<64, 64, 16, 4, 4, 0><<<dim3(cdiv(N_ALLc, 64), 4), 256>>>(
        h1wp, 256, wt2, 256, hp2, 256, N_ALLc, 256, 256, nullptr);
    esd_kernel<<<N_ALLc, 256>>>(hp2, as2, ad2, es2, ed2, N_ALLc);
    {
        int MW = (N_ALLc + 31) / 32;
        size_t sm = (size_t)(8 * N_ALLc + 8 * MW + 64 + 8 + 2048 + 256) * 4;
        gat_kernel<1><<<cdiv(N_ALLc, 8), 256, sm>>>(
            hp2, es2, ed2, wpadj, out + AWP_OFF, h2w, b2, N_ALLc);
    }

    // x
    xnorm_kernel<<<BATCHc / 8, 256>>>(uwa, h2w, out + X_OFF);

    // batch GEMMs
    sgemm2_kernel<128, 128, 16, 8, 8, 0><<<dim3(128, 1), 256>>>(
        out + X_OFF, 256, Ws1, 128, outcat, 256, BATCHc, 128, 256, bs1);
    sgemm2_kernel<128, 128, 16, 8, 8, 0><<<dim3(128, 1), 256>>>(
        sent, 768, Ws2, 128, outcat + 128, 256, BATCHc, 128, 768, bs2);

    sgemm2_kernel<128, 64, 16, 8, 4, 0><<<dim3(128, 1), 256>>>(
        outcat, 256, Wf1, 64, out + O1N_OFF, 64, BATCHc, 64, 128, bf1);
    sgemm2_kernel<128, 64, 16, 8, 4, 0><<<dim3(128, 1), 256>>>(
        outcat + 128, 256, Wf1, 64, out + O2N_OFF, 64, BATCHc, 64, 128, bf1);

    sgemm2_kernel<128, 128, 16, 8, 8, 1><<<dim3(128, 1), 256>>>(
        outcat, 256, Wfa, 128, tg, 128, BATCHc, 128, 256, bfa);

    xt_kernel<<<BATCHc / 8, 256>>>(tg, Wfb, bfb, out + XT_OFF);
}

// round 17
// speedup vs baseline: 1.4885x; 1.3328x over previous
#include <cuda_runtime.h>

#define N_Pc  2048
#define N_Wc  89
#define N_ALLc 2137
#define BATCHc 16384
#define E2c   768
#define UWc   313

#define O1N_OFF 0L
#define O2N_OFF 1048576L
#define XT_OFF  2097152L
#define APP_OFF 2179072L
#define AWP_OFF 35733504L
#define X_OFF   72267656L

// -------------------- scratch --------------------
__device__ float g_wt1[256 * 256];
__device__ float g_wt2[256 * 256];
__device__ float g_hp1[N_Pc * 256];
__device__ float g_hp2[N_ALLc * 256];
__device__ float g_h1wp[N_ALLc * 256];
__device__ float g_es1[8 * N_Pc];
__device__ float g_ed1[8 * N_Pc];
__device__ float g_es2[8 * N_ALLc];
__device__ float g_ed2[8 * N_ALLc];
__device__ float g_h2w[N_Wc * 32];
__device__ float g_h2p[8 * N_Wc * 32];
__device__ float g_outcat[BATCHc * 256];
__device__ float g_tg[BATCHc * 128];

// -------------------- fast exp (FMA pipe) --------------------
__device__ __forceinline__ float fast_exp(float x) {
    float y = x * 1.4426950408889634f;
    float t = y + 12582912.0f;
    int   ei = __float_as_int(t) - 0x4B400000;
    float r = t - 12582912.0f;
    float g = y - r;
    float p = 1.3333558146e-3f;
    p = fmaf(p, g, 9.6181291076e-3f);
    p = fmaf(p, g, 5.5504108664e-2f);
    p = fmaf(p, g, 2.4022650696e-1f);
    p = fmaf(p, g, 6.9314718056e-1f);
    p = fmaf(p, g, 1.0f);
    return p * __int_as_float(0x3f800000 + (ei << 23));
}

// -------------------- helpers --------------------
__global__ void wtrans_kernel(const float* __restrict__ w, float* __restrict__ wt) {
    int idx = blockIdx.x * 256 + threadIdx.x;
    int k = idx >> 8;
    int j = idx & 255;
    wt[idx] = w[((j >> 5) * 256 + k) * 32 + (j & 31)];
}

__global__ void copy_kernel(float* __restrict__ dst, const float* __restrict__ src, int n) {
    int i = blockIdx.x * 256 + threadIdx.x;
    if (i < n) dst[i] = src[i];
}

__global__ void esd_kernel(const float* __restrict__ hp,
                           const float* __restrict__ a_src,
                           const float* __restrict__ a_dst,
                           float* __restrict__ e_src,
                           float* __restrict__ e_dst, int N) {
    int n = blockIdx.x;
    int warp = threadIdx.x >> 5, lane = threadIdx.x & 31;
    float v = hp[(long)n * 256 + warp * 32 + lane];
    float s = v * a_src[warp * 32 + lane];
    float d = v * a_dst[warp * 32 + lane];
#pragma unroll
    for (int off = 16; off; off >>= 1) {
        s += __shfl_xor_sync(0xffffffffu, s, off);
        d += __shfl_xor_sync(0xffffffffu, d, off);
    }
    if (lane == 0) {
        e_src[warp * N + n] = s;
        e_dst[warp * N + n] = d;
    }
}

// -------------------- GAT attention (normalize + write only) --------------------
__global__ void gat_attn_kernel(const float* __restrict__ e_src,
                                const float* __restrict__ e_dst,
                                const int* __restrict__ adj,
                                float* __restrict__ attn_out,
                                int N) {
    extern __shared__ float smem[];
    const int MW = (N + 31) >> 5;
    float4* p4 = (float4*)smem;                 // 2*N float4
    float* fp = smem + 8 * N;
    unsigned* mask = (unsigned*)fp;             // 8*MW
    float* wsum = fp + 8 * MW;                  // 64
    float* sinv = wsum + 64;                    // 8

    const int tid = threadIdx.x;
    const int warp = tid >> 5;
    const int lane = tid & 31;
    const int row0 = blockIdx.x * 8;
    const int nr = min(8, N - row0);

#pragma unroll
    for (int r = 0; r < 8; r++) {
        int row = row0 + r;
        for (int base = warp * 32; base < MW * 32; base += 256) {
            int m = base + lane;
            int v = (row < N && m < N) ? adj[(long)row * N + m] : 0;
            unsigned bal = __ballot_sync(0xffffffffu, v > 0);
            if (lane == 0) mask[r * MW + (base >> 5)] = bal;
        }
    }
    __syncthreads();

    for (int h = 0; h < 8; h++) {
        float es[8], ls[8];
#pragma unroll
        for (int r = 0; r < 8; r++) {
            es[r] = (row0 + r < N) ? e_src[h * N + row0 + r] : 0.f;
            ls[r] = 0.f;
        }

        for (int m = tid; m < N; m += 256) {
            float ed = e_dst[h * N + m];
            int w = m >> 5;
            unsigned bit = 1u << (m & 31);
            float pv[8];
#pragma unroll
            for (int r = 0; r < 8; r++) {
                float e = es[r] + ed;
                e = fmaxf(e, 0.2f * e);
                pv[r] = (mask[r * MW + w] & bit) ? fast_exp(e) : 0.f;
                ls[r] += pv[r];
            }
            p4[m]     = make_float4(pv[0], pv[1], pv[2], pv[3]);
            p4[N + m] = make_float4(pv[4], pv[5], pv[6], pv[7]);
        }
#pragma unroll
        for (int off = 16; off; off >>= 1)
#pragma unroll
            for (int r = 0; r < 8; r++) ls[r] += __shfl_xor_sync(0xffffffffu, ls[r], off);
        if (lane == 0)
#pragma unroll
            for (int r = 0; r < 8; r++) wsum[warp * 8 + r] = ls[r];
        __syncthreads();
        if (tid < 8) {
            float s = 0.f;
#pragma unroll
            for (int w = 0; w < 8; w++) s += wsum[w * 8 + tid];
            sinv[tid] = (s > 0.f) ? (1.f / s) : 0.f;
        }
        __syncthreads();

        float sv[8];
#pragma unroll
        for (int r = 0; r < 8; r++) sv[r] = sinv[r];

        long ab = ((long)h * N + row0) * (long)N;
        for (int m = tid; m < N; m += 256) {
            float4 pa = p4[m], pb = p4[N + m];
            float pv[8] = {pa.x, pa.y, pa.z, pa.w, pb.x, pb.y, pb.z, pb.w};
#pragma unroll
            for (int r = 0; r < 8; r++)
                if (r < nr) attn_out[ab + (long)r * N + m] = pv[r] * sv[r];
        }
        __syncthreads();
    }
}

// -------------------- attn @ hp per-head skinny GEMM --------------------
// MODE 0: out rows 0..N-1, elu(v+bias) -> h1wp[(89+row)*256 + h*32+o]
// MODE 1: out rows 0..88 raw -> g_h2p[(h*89+row)*32+o]
template <int MODE>
__global__ void apgemm_kernel(const float* __restrict__ attn,
                              const float* __restrict__ hp,
                              float* __restrict__ dst,
                              const float* __restrict__ bias,
                              int N) {
    __shared__ float As[128][33];
    __shared__ float Bs[32][32];
    const int tid = threadIdx.x;            // 128 threads
    const int h = blockIdx.y;
    const int m0 = blockIdx.x * 128;
    const int tx = tid & 7;
    const int ty = tid >> 3;
    const long abase = (long)h * N * N;

    float acc[8][4];
#pragma unroll
    for (int i = 0; i < 8; i++)
#pragma unroll
        for (int j = 0; j < 4; j++) acc[i][j] = 0.f;

    for (int k0 = 0; k0 < N; k0 += 32) {
#pragma unroll
        for (int i = 0; i < 8; i++) {
            int idx = tid + i * 128;
            int row = idx >> 3;
            int col = (idx & 7) * 4;
            if (MODE == 0) {
                float4 v = *(const float4*)(attn + abase + (long)(m0 + row) * N + k0 + col);
                As[row][col + 0] = v.x;
                As[row][col + 1] = v.y;
                As[row][col + 2] = v.z;
                As[row][col + 3] = v.w;
            } else {
#pragma unroll
                for (int c = 0; c < 4; c++) {
                    int kk = k0 + col + c;
                    As[row][col + c] = (m0 + row < N_Wc && kk < N)
                        ? attn[abase + (long)(m0 + row) * N + kk] : 0.f;
                }
            }
        }
#pragma unroll
        for (int i = 0; i < 2; i++) {
            int idx = tid + i * 128;
            int br = idx >> 3;
            int bc = (idx & 7) * 4;
            int kk = k0 + br;
            float4 v = make_float4(0.f, 0.f, 0.f, 0.f);
            if (MODE == 0 || kk < N)
                v = *(const float4*)(hp + (long)kk * 256 + h * 32 + bc);
            *(float4*)&Bs[br][bc] = v;
        }
        __syncthreads();
#pragma unroll
        for (int k = 0; k < 32; k++) {
            float rb[4];
            *(float4*)rb = *(const float4*)&Bs[k][tx * 4];
            float ra[8];
#pragma unroll
            for (int i = 0; i < 8; i++) ra[i] = As[ty * 8 + i][k];
#pragma unroll
            for (int i = 0; i < 8; i++)
#pragma unroll
                for (int j = 0; j < 4; j++) acc[i][j] = fmaf(ra[i], rb[j], acc[i][j]);
        }
        __syncthreads();
    }

#pragma unroll
    for (int i = 0; i < 8; i++) {
        int row = m0 + ty * 8 + i;
        if (MODE == 0) {
#pragma unroll
            for (int j = 0; j < 4; j++) {
                float v = acc[i][j] + bias[tx * 4 + j];
                dst[(long)(N_Wc + row) * 256 + h * 32 + tx * 4 + j] =
                    (v > 0.f) ? v : (fast_exp(v) - 1.f);
            }
        } else if (row < N_Wc) {
#pragma unroll
            for (int j = 0; j < 4; j++)
                dst[(long)(h * N_Wc + row) * 32 + tx * 4 + j] = acc[i][j];
        }
    }
}

__global__ void h2mean_kernel(const float* __restrict__ p,
                              const float* __restrict__ b2,
                              float* __restrict__ h2w) {
    int i = blockIdx.x * 256 + threadIdx.x;
    if (i < N_Wc * 32) {
        float s = 0.f;
#pragma unroll
        for (int h = 0; h < 8; h++) s += p[h * N_Wc * 32 + i];
        h2w[i] = s * 0.125f + b2[i & 31];
    }
}

// -------------------- SGEMM: BK=8, TM=TN=8, double-buffered --------------------
template <int BM, int BN, int ACT>
__global__ void sgemm3_kernel(const float* __restrict__ A, int lda,
                              const float* __restrict__ B, int ldb,
                              float* __restrict__ C, int ldc,
                              int M, int N, int K,
                              const float* __restrict__ bias) {
    constexpr int BK = 8;
    constexpr int THREADS = (BM / 8) * (BN / 8);
    constexpr int LA = BM * BK / (4 * THREADS);
    constexpr int LB = BN * BK / (4 * THREADS);
    __shared__ __align__(16) float As[2][BK][BM];
    __shared__ __align__(16) float Bs[2][BK][BN];
    const int tid = threadIdx.x;
    const int m0 = blockIdx.x * BM;
    const int n0 = blockIdx.y * BN;
    const int tx = tid % (BN / 8);
    const int ty = tid / (BN / 8);

    float4 pa[LA], pb[LB];
    float acc[8][8];
#pragma unroll
    for (int i = 0; i < 8; i++)
#pragma unroll
        for (int j = 0; j < 8; j++) acc[i][j] = 0.f;

    auto loadG = [&](int k0) {
#pragma unroll
        for (int i = 0; i < LA; i++) {
            int idx = tid + i * THREADS;
            int arow = idx / (BK / 4);
            int acol = (idx % (BK / 4)) * 4;
            int grow = m0 + arow;
            pa[i] = (grow < M) ? *(const float4*)(A + (long)grow * lda + k0 + acol)
                               : make_float4(0.f, 0.f, 0.f, 0.f);
        }
#pragma unroll
        for (int i = 0; i < LB; i++) {
            int idx = tid + i * THREADS;
            int brow = idx / (BN / 4);
            int bcol = (idx % (BN / 4)) * 4;
            pb[i] = *(const float4*)(B + (long)(k0 + brow) * ldb + n0 + bcol);
        }
    };
    auto storeS = [&](int buf) {
#pragma unroll
        for (int i = 0; i < LA; i++) {
            int idx = tid + i * THREADS;
            int arow = idx / (BK / 4);
            int acol = (idx % (BK / 4)) * 4;
            As[buf][acol + 0][arow] = pa[i].x;
            As[buf][acol + 1][arow] = pa[i].y;
            As[buf][acol + 2][arow] = pa[i].z;
            As[buf][acol + 3][arow] = pa[i].w;
        }
#pragma unroll
        for (int i = 0; i < LB; i++) {
            int idx = tid + i * THREADS;
            int brow = idx / (BN / 4);
            int bcol = (idx % (BN / 4)) * 4;
            *(float4*)&Bs[buf][brow][bcol] = pb[i];
        }
    };

    loadG(0);
    storeS(0);
    __syncthreads();

    const int nt = K / BK;
    for (int t = 0; t < nt; t++) {
        int cur = t & 1;
        if (t + 1 < nt) loadG((t + 1) * BK);
#pragma unroll
        for (int k = 0; k < BK; k++) {
            float ra[8], rb[8];
            *(float4*)&ra[0] = *(const float4*)&As[cur][k][ty * 8];
            *(float4*)&ra[4] = *(const float4*)&As[cur][k][ty * 8 + 4];
            *(float4*)&rb[0] = *(const float4*)&Bs[cur][k][tx * 4];
            *(float4*)&rb[4] = *(const float4*)&Bs[cur][k][BN / 2 + tx * 4];
#pragma unroll
            for (int i = 0; i < 8; i++)
#pragma unroll
                for (int j = 0; j < 8; j++) acc[i][j] = fmaf(ra[i], rb[j], acc[i][j]);
        }
        if (t + 1 < nt) storeS(1 - cur);
        __syncthreads();
    }

#pragma unroll
    for (int i = 0; i < 8; i++) {
        int row = m0 + ty * 8 + i;
        if (row >= M) continue;
#pragma unroll
        for (int j = 0; j < 8; j++) {
            int col = n0 + ((j < 4) ? (tx * 4 + j) : (BN / 2 + tx * 4 + j - 4));
            float v = acc[i][j];
            if (bias) v += bias[col];
            if (ACT == 1) v = fmaxf(v, 0.f);
            C[(long)row * ldc + col] = v;
        }
    }
}

// -------------------- x normalization --------------------
__global__ void xnorm_kernel(const float* __restrict__ uwa,
                             const float* __restrict__ h2w,
                             float* __restrict__ xout) {
    __shared__ float sh2[N_Wc * 32];
    __shared__ float srow[8][320];
    int tid = threadIdx.x;
    for (int i = tid; i < N_Wc * 32; i += 256) sh2[i] = h2w[i];
    int warp = tid >> 5, lane = tid & 31;
    int b = blockIdx.x * 8 + warp;
    for (int k = lane; k < UWc; k += 32) srow[warp][k] = uwa[(long)b * UWc + k];
    __syncthreads();

    float x0 = 0.f;
    for (int k = 0; k < N_Wc; k++) x0 = fmaf(srow[warp][k], sh2[k * 32 + lane], x0);
    float part = x0;
    for (int k = N_Wc + lane; k < UWc; k += 32) part += srow[warp][k];
#pragma unroll
    for (int off = 16; off; off >>= 1) part += __shfl_xor_sync(0xffffffffu, part, off);
    float inv = 1.f / part;
    xout[(long)b * 256 + lane] = x0 * inv;
    for (int k = lane; k < 224; k += 32)
        xout[(long)b * 256 + 32 + k] = srow[warp][N_Wc + k] * inv;
}

// -------------------- x_temp final --------------------
__global__ void xt_kernel(const float* __restrict__ t,
                          const float* __restrict__ Wfb,
                          const float* __restrict__ bfb,
                          float* __restrict__ out) {
    __shared__ float sw[128 * 5];
    __shared__ float sb[5];
    int tid = threadIdx.x;
    for (int i = tid; i < 640; i += 256) sw[i] = Wfb[i];
    if (tid < 5) sb[tid] = bfb[tid];
    __syncthreads();
    int warp = tid >> 5, lane = tid & 31;
    int b = blockIdx.x * 8 + warp;
    float acc[5] = {0.f, 0.f, 0.f, 0.f, 0.f};
    for (int k = lane; k < 128; k += 32) {
        float tv = t[(long)b * 128 + k];
#pragma unroll
        for (int j = 0; j < 5; j++) acc[j] = fmaf(tv, sw[k * 5 + j], acc[j]);
    }
#pragma unroll
    for (int off = 16; off; off >>= 1)
#pragma unroll
        for (int j = 0; j < 5; j++) acc[j] += __shfl_xor_sync(0xffffffffu, acc[j], off);
    if (lane < 5) out[(long)b * 5 + lane] = acc[lane] + sb[lane];
}

// -------------------- host launch --------------------
static inline int cdiv(int a, int b) { return (a + b - 1) / b; }

extern "C" void kernel_launch(void* const* d_in, const int* in_sizes, int n_in,
                              void* d_out, int out_size) {
    const float* pern  = (const float*)d_in[0];
    const float* wordf = (const float*)d_in[1];
    const int*   padj  = (const int*)d_in[2];
    const int*   wpadj = (const int*)d_in[3];
    const float* uwa   = (const float*)d_in[4];
    const float* sent  = (const float*)d_in[5];
    const float* w1    = (const float*)d_in[6];
    const float* as1   = (const float*)d_in[7];
    const float* ad1   = (const float*)d_in[8];
    const float* b1    = (const float*)d_in[9];
    const float* w2    = (const float*)d_in[10];
    const float* as2   = (const float*)d_in[11];
    const float* ad2   = (const float*)d_in[12];
    const float* b2    = (const float*)d_in[13];
    const float* Ws1   = (const float*)d_in[14];
    const float* bs1   = (const float*)d_in[15];
    const float* Ws2   = (const float*)d_in[16];
    const float* bs2   = (const float*)d_in[17];
    const float* Wf1   = (const float*)d_in[18];
    const float* bf1   = (const float*)d_in[19];
    const float* Wfa   = (const float*)d_in[20];
    const float* bfa   = (const float*)d_in[21];
    const float* Wfb   = (const float*)d_in[22];
    const float* bfb   = (const float*)d_in[23];
    float* out = (float*)d_out;

    float *wt1, *wt2, *hp1, *hp2, *h1wp, *es1, *ed1, *es2, *ed2, *h2w, *h2p, *outcat, *tg;
    cudaGetSymbolAddress((void**)&wt1, g_wt1);
    cudaGetSymbolAddress((void**)&wt2, g_wt2);
    cudaGetSymbolAddress((void**)&hp1, g_hp1);
    cudaGetSymbolAddress((void**)&hp2, g_hp2);
    cudaGetSymbolAddress((void**)&h1wp, g_h1wp);
    cudaGetSymbolAddress((void**)&es1, g_es1);
    cudaGetSymbolAddress((void**)&ed1, g_ed1);
    cudaGetSymbolAddress((void**)&es2, g_es2);
    cudaGetSymbolAddress((void**)&ed2, g_ed2);
    cudaGetSymbolAddress((void**)&h2w, g_h2w);
    cudaGetSymbolAddress((void**)&h2p, g_h2p);
    cudaGetSymbolAddress((void**)&outcat, g_outcat);
    cudaGetSymbolAddress((void**)&tg, g_tg);

    cudaFuncSetAttribute(gat_attn_kernel, cudaFuncAttributeMaxDynamicSharedMemorySize, 96 * 1024);

    wtrans_kernel<<<256, 256>>>(w1, wt1);
    wtrans_kernel<<<256, 256>>>(w2, wt2);
    copy_kernel<<<cdiv(N_Wc * 256, 256), 256>>>(h1wp, wordf, N_Wc * 256);

    // GAT1
    sgemm3_kernel<64, 128, 0><<<dim3(32, 2), 128>>>(
        pern, 256, wt1, 256, hp1, 256, N_Pc, 256, 256, nullptr);
    esd_kernel<<<N_Pc, 256>>>(hp1, as1, ad1, es1, ed1, N_Pc);
    {
        int MW = (N_Pc + 31) / 32;
        size_t sm = (size_t)(8 * N_Pc + 8 * MW + 64 + 8) * 4;
        gat_attn_kernel<<<cdiv(N_Pc, 8), 256, sm>>>(es1, ed1, padj, out + APP_OFF, N_Pc);
    }
    apgemm_kernel<0><<<dim3(16, 8), 128>>>(out + APP_OFF, hp1, h1wp, b1, N_Pc);

    // GAT2
    sgemm3_kernel<64, 128, 0><<<dim3(cdiv(N_ALLc, 64), 2), 128>>>(
        h1wp, 256, wt2, 256, hp2, 256, N_ALLc, 256, 256, nullptr);
    esd_kernel<<<N_ALLc, 256>>>(hp2, as2, ad2, es2, ed2, N_ALLc);
    {
        int MW = (N_ALLc + 31) / 32;
        size_t sm = (size_t)(8 * N_ALLc + 8 * MW + 64 + 8) * 4;
        gat_attn_kernel<<<cdiv(N_ALLc, 8), 256, sm>>>(es2, ed2, wpadj, out + AWP_OFF, N_ALLc);
    }
    apgemm_kernel<1><<<dim3(1, 8), 128>>>(out + AWP_OFF, hp2, h2p, b2, N_ALLc);
    h2mean_kernel<<<cdiv(N_Wc * 32, 256), 256>>>(h2p, b2, h2w);

    // x
    xnorm_kernel<<<BATCHc / 8, 256>>>(uwa, h2w, out + X_OFF);

    // batch GEMMs
    sgemm3_kernel<64, 128, 0><<<dim3(256, 1), 128>>>(
        out + X_OFF, 256, Ws1, 128, outcat, 256, BATCHc, 128, 256, bs1);
    sgemm3_kernel<64, 128, 0><<<dim3(256, 1), 128>>>(
        sent, 768, Ws2, 128, outcat + 128, 256, BATCHc, 128, 768, bs2);

    sgemm3_kernel<128, 64, 0><<<dim3(128, 1), 128>>>(
        outcat, 256, Wf1, 64, out + O1N_OFF, 64, BATCHc, 64, 128, bf1);
    sgemm3_kernel<128, 64, 0><<<dim3(128, 1), 128>>>(
        outcat + 128, 256, Wf1, 64, out + O2N_OFF, 64, BATCHc, 64, 128, bf1);

    sgemm3_kernel<64, 128, 1><<<dim3(256, 1), 128>>>(
        outcat, 256, Wfa, 128, tg, 128, BATCHc, 128, 256, bfa);

    xt_kernel<<<BATCHc / 8, 256>>>(tg, Wfb, bfb, out + XT_OFF);
}